// round 1
// baseline (speedup 1.0000x reference)
#include <cuda_runtime.h>
#include <math.h>

// ---------------- problem constants ----------------
#define TSTEPS 1000
#define NIN    4096
#define RN     4000            // R1 == R2
#define OUTW   (2*RN)
#define ALPHA  0.5f

// ---------------- persistent kernel config ----------------
#define NBLK   296             // 2 blocks/SM on 148 SMs (GB300 has 152 -> safe)
#define NTHR   512
#define NWARPB (NTHR/32)
#define TOTW   (NBLK*NWARPB)

#define JT     8               // j-tiles of 512 for dense phase
#define KCH    (NBLK/JT)       // 37 K-chunks
#define CHUNK  ((RN + KCH - 1)/KCH)   // 109

// nnz ~ 0.1*16M = 1.6M expected (sigma ~1.2K); huge margin
#define NNZ_CAP 1800000

// ---------------- device scratch (static; no allocations) ----------------
__device__ float          d_vals1[NNZ_CAP];
__device__ unsigned short d_rows1[NNZ_CAP];
__device__ float          d_vals2[NNZ_CAP];
__device__ unsigned short d_rows2[NNZ_CAP];
__device__ int            d_colptr1[RN+1];
__device__ int            d_colptr2[RN+1];
__device__ int            d_cnt1[RN];
__device__ int            d_cnt2[RN];
__device__ float          d_U1[TSTEPS*RN];   // x @ Win1 precomputed (16 MB)
__device__ float          d_v1[2][RN];
__device__ float          d_v2[2][RN];
__device__ float          d_z2[RN];
__device__ unsigned int   g_bar_in;
__device__ volatile unsigned int g_bar_out;

// ---------------- init ----------------
__global__ void initKernel() {
    int idx = blockIdx.x * blockDim.x + threadIdx.x;
    if (idx < RN) {
        d_v1[0][idx] = 0.f; d_v1[1][idx] = 0.f;
        d_v2[0][idx] = 0.f; d_v2[1][idx] = 0.f;
        d_z2[idx]    = 0.f;
    }
    if (idx == 0) { g_bar_in = 0u; g_bar_out = 0u; }
}

// ---------------- sparse build: count nnz per column ----------------
__global__ void countKernel(const float* __restrict__ W1,
                            const float* __restrict__ W2) {
    int j = blockIdx.x * blockDim.x + threadIdx.x;
    if (j < RN) {
        int c = 0;
        for (int i = 0; i < RN; i++) c += (W1[(size_t)i*RN + j] != 0.f);
        d_cnt1[j] = c;
    } else if (j < 2*RN) {
        int jj = j - RN;
        int c = 0;
        for (int i = 0; i < RN; i++) c += (W2[(size_t)i*RN + jj] != 0.f);
        d_cnt2[jj] = c;
    }
}

// ---------------- exclusive scan (one block per matrix) ----------------
__global__ void scanKernel() {
    __shared__ int sA[4096], sB[4096];
    const int* cnt  = (blockIdx.x == 0) ? d_cnt1 : d_cnt2;
    int* colptr     = (blockIdx.x == 0) ? d_colptr1 : d_colptr2;
    int tid = threadIdx.x;
    for (int i = tid; i < 4096; i += blockDim.x) sA[i] = (i < RN) ? cnt[i] : 0;
    __syncthreads();
    int* src = sA; int* dst = sB;
    for (int off = 1; off < 4096; off <<= 1) {
        for (int i = tid; i < 4096; i += blockDim.x)
            dst[i] = src[i] + (i >= off ? src[i - off] : 0);
        __syncthreads();
        int* t = src; src = dst; dst = t;
    }
    for (int i = tid; i < RN; i += blockDim.x) colptr[i + 1] = src[i];
    if (tid == 0) colptr[0] = 0;
}

// ---------------- sparse build: fill CSC ----------------
__global__ void fillKernel(const float* __restrict__ W1,
                           const float* __restrict__ W2) {
    int j = blockIdx.x * blockDim.x + threadIdx.x;
    if (j < RN) {
        int p = d_colptr1[j];
        for (int i = 0; i < RN; i++) {
            float w = W1[(size_t)i*RN + j];
            if (w != 0.f) { d_vals1[p] = w; d_rows1[p] = (unsigned short)i; p++; }
        }
    } else if (j < 2*RN) {
        int jj = j - RN;
        int p = d_colptr2[jj];
        for (int i = 0; i < RN; i++) {
            float w = W2[(size_t)i*RN + jj];
            if (w != 0.f) { d_vals2[p] = w; d_rows2[p] = (unsigned short)i; p++; }
        }
    }
}

// ---------------- SGEMM: d_U1[1000,4000] = x[1000,4096] @ Win1[4096,4000] ----------------
__global__ __launch_bounds__(256) void sgemmK(const float* __restrict__ A,
                                              const float* __restrict__ B) {
    const int M = TSTEPS, N = RN, K = NIN;
    __shared__ float As[8][128];
    __shared__ float Bs[8][128];
    int tid = threadIdx.x;
    int tx = tid % 16, ty = tid / 16;
    int row0 = blockIdx.y * 128, col0 = blockIdx.x * 128;
    float acc[8][8];
#pragma unroll
    for (int i = 0; i < 8; i++)
#pragma unroll
        for (int j = 0; j < 8; j++) acc[i][j] = 0.f;

    int aRow = tid >> 1;            // 0..127
    int aCol = (tid & 1) * 4;       // 0 or 4
    int bRow = tid >> 5;            // 0..7
    int bCol = (tid & 31) * 4;      // 0..124

    for (int k0 = 0; k0 < K; k0 += 8) {
        float4 a4 = make_float4(0.f, 0.f, 0.f, 0.f);
        if (row0 + aRow < M)
            a4 = *(const float4*)(A + (size_t)(row0 + aRow) * K + k0 + aCol);
        As[aCol + 0][aRow] = a4.x; As[aCol + 1][aRow] = a4.y;
        As[aCol + 2][aRow] = a4.z; As[aCol + 3][aRow] = a4.w;

        float4 b4 = make_float4(0.f, 0.f, 0.f, 0.f);
        if (col0 + bCol < N)
            b4 = *(const float4*)(B + (size_t)(k0 + bRow) * N + col0 + bCol);
        *(float4*)(&Bs[bRow][bCol]) = b4;
        __syncthreads();

#pragma unroll
        for (int kk = 0; kk < 8; kk++) {
            float ar[8], br[8];
            *(float4*)(ar)     = *(float4*)(&As[kk][ty * 4]);
            *(float4*)(ar + 4) = *(float4*)(&As[kk][64 + ty * 4]);
            *(float4*)(br)     = *(float4*)(&Bs[kk][tx * 4]);
            *(float4*)(br + 4) = *(float4*)(&Bs[kk][64 + tx * 4]);
#pragma unroll
            for (int i = 0; i < 8; i++)
#pragma unroll
                for (int j = 0; j < 8; j++) acc[i][j] += ar[i] * br[j];
        }
        __syncthreads();
    }
#pragma unroll
    for (int i = 0; i < 8; i++) {
        int r = row0 + ((i < 4) ? (ty * 4 + i) : (64 + ty * 4 + i - 4));
        if (r >= M) continue;
#pragma unroll
        for (int half = 0; half < 2; half++) {
            int c = col0 + (half == 0 ? tx * 4 : 64 + tx * 4);
            if (c < N) {
                float4 v = make_float4(acc[i][half*4+0], acc[i][half*4+1],
                                       acc[i][half*4+2], acc[i][half*4+3]);
                *(float4*)(d_U1 + (size_t)r * N + c) = v;
            }
        }
    }
}

// ---------------- grid-wide barrier ----------------
__device__ __forceinline__ void grid_sync(unsigned int &gen) {
    __syncthreads();
    if (threadIdx.x == 0) {
        gen++;
        __threadfence();
        unsigned int arrived = atomicAdd(&g_bar_in, 1u) + 1u;
        if (arrived == gen * (unsigned int)NBLK) {
            g_bar_out = gen;                  // release
        } else {
            while (g_bar_out < gen) { }       // spin
        }
        __threadfence();
    }
    __syncthreads();
}

// ---------------- persistent ESN recurrence kernel ----------------
__global__ __launch_bounds__(NTHR, 2) void esnKernel(const float* __restrict__ Win2,
                                                     float* __restrict__ out) {
    unsigned int gen = 0;
    const int tid  = threadIdx.x;
    const int lane = tid & 31;
    const int gwarp = blockIdx.x * NWARPB + (tid >> 5);
    const int jt = blockIdx.x % JT;
    const int kc = blockIdx.x / JT;
    const int k0 = kc * CHUNK;
    const int k1 = (k0 + CHUNK < RN) ? (k0 + CHUNK) : RN;
    const int klen = k1 - k0;
    __shared__ float v1chunk[CHUNK];

    for (int t = 0; t < TSTEPS; t++) {
        const int pa = t & 1, pb = pa ^ 1;
        const float* __restrict__ v1o = d_v1[pa];
        float*       __restrict__ v1n = d_v1[pb];
        const float* __restrict__ v2o = d_v2[pa];
        float*       __restrict__ v2n = d_v2[pb];

        // ---- Phase A: sparse matvecs (v1 update + z2 sparse part) ----
        for (int o = gwarp; o < 2 * RN; o += TOTW) {
            float acc = 0.f;
            if (o < RN) {
                const int j  = o;
                const int pe = d_colptr1[j + 1];
                for (int p = d_colptr1[j] + lane; p < pe; p += 32)
                    acc += d_vals1[p] * __ldg(&v1o[d_rows1[p]]);
#pragma unroll
                for (int off = 16; off > 0; off >>= 1)
                    acc += __shfl_down_sync(0xffffffffu, acc, off);
                if (lane == 0) {
                    float z  = acc + d_U1[t * RN + j];
                    float vn = (1.f - ALPHA) * v1o[j] + ALPHA * tanhf(z);
                    v1n[j] = vn;
                    __stcs(&out[(size_t)t * OUTW + j], vn);
                }
            } else {
                const int j  = o - RN;
                const int pe = d_colptr2[j + 1];
                for (int p = d_colptr2[j] + lane; p < pe; p += 32)
                    acc += d_vals2[p] * __ldg(&v2o[d_rows2[p]]);
#pragma unroll
                for (int off = 16; off > 0; off >>= 1)
                    acc += __shfl_down_sync(0xffffffffu, acc, off);
                if (lane == 0) d_z2[j] = acc;
            }
        }
        grid_sync(gen);

        // ---- Phase B: dense  z2 += v1n @ Win2  (K-chunked partials) ----
        for (int i = tid; i < klen; i += NTHR) v1chunk[i] = v1n[k0 + i];
        __syncthreads();
        {
            const int j = jt * NTHR + tid;
            if (j < RN) {
                float acc = 0.f;
                const float* wp = Win2 + (size_t)k0 * RN + j;
#pragma unroll 4
                for (int i = 0; i < klen; i++)
                    acc += v1chunk[i] * wp[(size_t)i * RN];
                atomicAdd(&d_z2[j], acc);
            }
        }
        grid_sync(gen);

        // ---- Phase C: v2 finalize + output ----
        {
            const int j = blockIdx.x * NTHR + tid;
            if (j < RN) {
                float vn = (1.f - ALPHA) * v2o[j] + ALPHA * tanhf(d_z2[j]);
                v2n[j] = vn;
                __stcs(&out[(size_t)t * OUTW + RN + j], vn);
            }
        }
        grid_sync(gen);
    }
}

// ---------------- launch ----------------
extern "C" void kernel_launch(void* const* d_in, const int* in_sizes, int n_in,
                              void* d_out, int out_size) {
    const float* x    = (const float*)d_in[0];
    const float* Win1 = (const float*)d_in[1];
    const float* W1   = (const float*)d_in[2];
    const float* Win2 = (const float*)d_in[3];
    const float* W2   = (const float*)d_in[4];
    float* out = (float*)d_out;
    (void)in_sizes; (void)n_in; (void)out_size;

    initKernel<<<(RN + 255) / 256, 256>>>();
    countKernel<<<(2 * RN + 255) / 256, 256>>>(W1, W2);
    scanKernel<<<2, 1024>>>();
    fillKernel<<<(2 * RN + 255) / 256, 256>>>(W1, W2);

    dim3 gg((RN + 127) / 128, (TSTEPS + 127) / 128);
    sgemmK<<<gg, 256>>>(x, Win1);

    esnKernel<<<NBLK, NTHR>>>(Win2, out);
}

// round 2
// speedup vs baseline: 1.6815x; 1.6815x over previous
#include <cuda_runtime.h>
#include <math.h>

// ---------------- problem constants ----------------
#define TSTEPS 1000
#define NIN    4096
#define RN     4000            // R1 == R2
#define OUTW   (2*RN)
#define ALPHA  0.5f

// ---------------- persistent kernel config ----------------
#define NBLK   125             // 125 tiles of 32 columns: 125*32 = 4000 exactly
#define NTHR   1024

// nnz ~ 0.1*16M = 1.6M expected (sigma ~1.2K); huge margin
#define NNZ_CAP 1800000

// ---------------- device scratch (static; no allocations) ----------------
__device__ float          d_vals1[NNZ_CAP];
__device__ unsigned short d_rows1[NNZ_CAP];
__device__ float          d_vals2[NNZ_CAP];
__device__ unsigned short d_rows2[NNZ_CAP];
__device__ int            d_colptr1[RN+1];
__device__ int            d_colptr2[RN+1];
__device__ int            d_cntW1[8*RN];      // per-(warp-range, column) counts
__device__ int            d_cntW2[8*RN];
__device__ float          d_U1[TSTEPS*RN];    // x @ Win1 precomputed (16 MB)
__device__ float          d_v1[2][RN];
__device__ float          d_v2[2][RN];
__device__ unsigned int   g_bar_in;
__device__ volatile unsigned int g_bar_out;

// ---------------- init ----------------
__global__ void initKernel() {
    int idx = blockIdx.x * blockDim.x + threadIdx.x;
    if (idx < RN) {
        d_v2[0][idx] = 0.f; d_v2[1][idx] = 0.f;
    }
    if (idx == 0) { g_bar_in = 0u; g_bar_out = 0u; }
}

// ---------------- sparse build: per-warp-range counts ----------------
// 250 blocks x 256 threads. Block handles 32 cols of one matrix; 8 warps split
// the 4000 rows into ranges of 500. Fully coalesced reads.
__global__ void countKernel(const float* __restrict__ W1,
                            const float* __restrict__ W2) {
    int b = blockIdx.x;
    const float* W; int* cntW; int j0;
    if (b < 125) { W = W1; cntW = d_cntW1; j0 = b * 32; }
    else         { W = W2; cntW = d_cntW2; j0 = (b - 125) * 32; }
    int w = threadIdx.x >> 5, lane = threadIdx.x & 31;
    int j = j0 + lane;
    int c = 0;
    int i0 = w * 500, i1 = i0 + 500;
    for (int i = i0; i < i1; i++) c += (W[(size_t)i * RN + j] != 0.f);
    cntW[w * RN + j] = c;
}

// ---------------- exclusive scan (one block per matrix) ----------------
__global__ void scanKernel() {
    __shared__ int sA[4096], sB[4096];
    const int* cntW = (blockIdx.x == 0) ? d_cntW1 : d_cntW2;
    int* colptr     = (blockIdx.x == 0) ? d_colptr1 : d_colptr2;
    int tid = threadIdx.x;
    for (int i = tid; i < 4096; i += blockDim.x) {
        int tot = 0;
        if (i < RN)
            for (int w = 0; w < 8; w++) tot += cntW[w * RN + i];
        sA[i] = tot;
    }
    __syncthreads();
    int* src = sA; int* dst = sB;
    for (int off = 1; off < 4096; off <<= 1) {
        for (int i = tid; i < 4096; i += blockDim.x)
            dst[i] = src[i] + (i >= off ? src[i - off] : 0);
        __syncthreads();
        int* t = src; src = dst; dst = t;
    }
    for (int i = tid; i < RN; i += blockDim.x) colptr[i + 1] = src[i];
    if (tid == 0) colptr[0] = 0;
}

// ---------------- sparse build: fill CSC (coalesced, warp-range bases) ------
__global__ void fillKernel(const float* __restrict__ W1,
                           const float* __restrict__ W2) {
    int b = blockIdx.x;
    const float* W; const int* cntW; const int* colptr;
    float* vals; unsigned short* rows; int j0;
    if (b < 125) { W = W1; cntW = d_cntW1; colptr = d_colptr1;
                   vals = d_vals1; rows = d_rows1; j0 = b * 32; }
    else         { W = W2; cntW = d_cntW2; colptr = d_colptr2;
                   vals = d_vals2; rows = d_rows2; j0 = (b - 125) * 32; }
    int w = threadIdx.x >> 5, lane = threadIdx.x & 31;
    int j = j0 + lane;
    int p = colptr[j];
    for (int w2 = 0; w2 < 8; w2++)
        if (w2 < w) p += cntW[w2 * RN + j];
    int i0 = w * 500, i1 = i0 + 500;
    for (int i = i0; i < i1; i++) {
        float v = W[(size_t)i * RN + j];
        if (v != 0.f) { vals[p] = v; rows[p] = (unsigned short)i; p++; }
    }
}

// ---------------- SGEMM: d_U1[1000,4000] = x[1000,4096] @ Win1[4096,4000] ----
__global__ __launch_bounds__(256) void sgemmK(const float* __restrict__ A,
                                              const float* __restrict__ B) {
    const int M = TSTEPS, N = RN, K = NIN;
    __shared__ float As[8][128];
    __shared__ float Bs[8][128];
    int tid = threadIdx.x;
    int tx = tid % 16, ty = tid / 16;
    int row0 = blockIdx.y * 128, col0 = blockIdx.x * 128;
    float acc[8][8];
#pragma unroll
    for (int i = 0; i < 8; i++)
#pragma unroll
        for (int j = 0; j < 8; j++) acc[i][j] = 0.f;

    int aRow = tid >> 1;
    int aCol = (tid & 1) * 4;
    int bRow = tid >> 5;
    int bCol = (tid & 31) * 4;

    for (int k0 = 0; k0 < K; k0 += 8) {
        float4 a4 = make_float4(0.f, 0.f, 0.f, 0.f);
        if (row0 + aRow < M)
            a4 = *(const float4*)(A + (size_t)(row0 + aRow) * K + k0 + aCol);
        As[aCol + 0][aRow] = a4.x; As[aCol + 1][aRow] = a4.y;
        As[aCol + 2][aRow] = a4.z; As[aCol + 3][aRow] = a4.w;

        float4 b4 = make_float4(0.f, 0.f, 0.f, 0.f);
        if (col0 + bCol < N)
            b4 = *(const float4*)(B + (size_t)(k0 + bRow) * N + col0 + bCol);
        *(float4*)(&Bs[bRow][bCol]) = b4;
        __syncthreads();

#pragma unroll
        for (int kk = 0; kk < 8; kk++) {
            float ar[8], br[8];
            *(float4*)(ar)     = *(float4*)(&As[kk][ty * 4]);
            *(float4*)(ar + 4) = *(float4*)(&As[kk][64 + ty * 4]);
            *(float4*)(br)     = *(float4*)(&Bs[kk][tx * 4]);
            *(float4*)(br + 4) = *(float4*)(&Bs[kk][64 + tx * 4]);
#pragma unroll
            for (int i = 0; i < 8; i++)
#pragma unroll
                for (int j = 0; j < 8; j++) acc[i][j] += ar[i] * br[j];
        }
        __syncthreads();
    }
#pragma unroll
    for (int i = 0; i < 8; i++) {
        int r = row0 + ((i < 4) ? (ty * 4 + i) : (64 + ty * 4 + i - 4));
        if (r >= M) continue;
#pragma unroll
        for (int half = 0; half < 2; half++) {
            int c = col0 + (half == 0 ? tx * 4 : 64 + tx * 4);
            if (c < N) {
                float4 v = make_float4(acc[i][half*4+0], acc[i][half*4+1],
                                       acc[i][half*4+2], acc[i][half*4+3]);
                *(float4*)(d_U1 + (size_t)r * N + c) = v;
            }
        }
    }
}

// ---------------- grid-wide barrier ----------------
__device__ __forceinline__ void grid_sync(unsigned int &gen) {
    __syncthreads();
    if (threadIdx.x == 0) {
        gen++;
        __threadfence();
        unsigned int arrived = atomicAdd(&g_bar_in, 1u) + 1u;
        if (arrived == gen * (unsigned int)NBLK) {
            g_bar_out = gen;                  // release
        } else {
            while (g_bar_out < gen) { }       // spin
        }
        __threadfence();
    }
    __syncthreads();
}

// ---------------- persistent ESN: one grid barrier per timestep ------------
// Block b owns columns [b*32, b*32+32) of BOTH reservoirs.
// Phase t (inputs: v1(t), v2(t-1)):
//   v2(t)   = 0.5 v2(t-1) + 0.5 tanh( v2(t-1)@W2 + v1(t)@Win2 )  [sparse+dense, block-local]
//   v1(t+1) = 0.5 v1(t)   + 0.5 tanh( v1(t)@W1 + U1[t+1] )       [sparse, block-local]
__global__ __launch_bounds__(NTHR, 1) void esnKernel(const float* __restrict__ Win2,
                                                     float* __restrict__ out) {
    __shared__ float  v1s[RN];
    __shared__ float  v2s[RN];
    __shared__ float4 red[256];     // 32 warps x 8 col-groups
    __shared__ float  ssum2[32];

    unsigned int gen = 0;
    const int tid  = threadIdx.x;
    const int lane = tid & 31;
    const int wrp  = tid >> 5;          // 0..31
    const int jq   = tid & 7;           // float4 col group within tile
    const int rw   = tid >> 3;          // 0..127 row slice
    const int j0   = blockIdx.x * 32;

    // ---- prologue: v1(0) = 0.5*tanh(U1[0]) ; out row 0 (v1 half) ----
    for (int j = blockIdx.x * NTHR + tid; j < RN; j += NBLK * NTHR) {
        float vn = ALPHA * tanhf(__ldg(&d_U1[j]));
        d_v1[0][j] = vn;
        __stcs(&out[j], vn);
    }
    grid_sync(gen);

    for (int t = 0; t < TSTEPS; t++) {
        const int pa = t & 1, pb = pa ^ 1;
        const float* __restrict__ v1o = d_v1[pa];   // v1(t)
        float*       __restrict__ v1n = d_v1[pb];   // v1(t+1)
        const float* __restrict__ v2o = d_v2[pa];   // v2(t-1)
        float*       __restrict__ v2n = d_v2[pb];   // v2(t)

        // ---- stage state vectors into smem (fresh from L2: __ldcg) ----
        {
            const float4* s1 = reinterpret_cast<const float4*>(v1o);
            const float4* s2 = reinterpret_cast<const float4*>(v2o);
            for (int i = tid; i < RN / 4; i += NTHR) {
                reinterpret_cast<float4*>(v1s)[i] = __ldcg(s1 + i);
                reinterpret_cast<float4*>(v2s)[i] = __ldcg(s2 + i);
            }
        }
        __syncthreads();

        // ---- dense: partial dots of Win2[:, j0..j0+32) with v1s ----
        {
            float4 acc = make_float4(0.f, 0.f, 0.f, 0.f);
            const float* wbase = Win2 + j0 + 4 * jq;
#pragma unroll 4
            for (int i = rw; i < RN; i += 128) {
                float v = v1s[i];
                float4 w4 = __ldcg(reinterpret_cast<const float4*>(wbase + (size_t)i * RN));
                acc.x += v * w4.x; acc.y += v * w4.y;
                acc.z += v * w4.z; acc.w += v * w4.w;
            }
            // intra-warp reduce over the 4 row-slices that share jq
#pragma unroll
            for (int off = 8; off <= 16; off <<= 1) {
                acc.x += __shfl_xor_sync(0xffffffffu, acc.x, off);
                acc.y += __shfl_xor_sync(0xffffffffu, acc.y, off);
                acc.z += __shfl_xor_sync(0xffffffffu, acc.z, off);
                acc.w += __shfl_xor_sync(0xffffffffu, acc.w, off);
            }
            if (lane < 8) red[wrp * 8 + jq] = acc;
        }

        // ---- sparse2: warp w handles v2-column j0+w ----
        {
            const int j  = j0 + wrp;
            const int ps = __ldg(&d_colptr2[j]);
            const int pe = __ldg(&d_colptr2[j + 1]);
            float acc = 0.f;
            for (int p = ps + lane; p < pe; p += 32)
                acc += __ldg(&d_vals2[p]) * v2s[__ldg(&d_rows2[p])];
#pragma unroll
            for (int off = 16; off > 0; off >>= 1)
                acc += __shfl_down_sync(0xffffffffu, acc, off);
            if (lane == 0) ssum2[wrp] = acc;
        }

        // ---- sparse1: warp w handles v1-column j0+w (skip on last step) ----
        if (t < TSTEPS - 1) {
            const int j  = j0 + wrp;
            const int ps = __ldg(&d_colptr1[j]);
            const int pe = __ldg(&d_colptr1[j + 1]);
            float acc = 0.f;
            for (int p = ps + lane; p < pe; p += 32)
                acc += __ldg(&d_vals1[p]) * v1s[__ldg(&d_rows1[p])];
#pragma unroll
            for (int off = 16; off > 0; off >>= 1)
                acc += __shfl_down_sync(0xffffffffu, acc, off);
            if (lane == 0) {
                float z  = acc + __ldg(&d_U1[(size_t)(t + 1) * RN + j]);
                float vn = (1.f - ALPHA) * v1s[j] + ALPHA * tanhf(z);
                v1n[j] = vn;
                __stcs(&out[(size_t)(t + 1) * OUTW + j], vn);
            }
        }
        __syncthreads();

        // ---- finalize v2(t): reduce dense partials + sparse, tanh ----
        if (tid < 32) {
            const int c = tid;
            float dsum = 0.f;
            const int q = c >> 2, comp = c & 3;
#pragma unroll 8
            for (int wp = 0; wp < 32; wp++) {
                float4 r4 = red[wp * 8 + q];
                dsum += (comp == 0) ? r4.x : (comp == 1) ? r4.y
                      : (comp == 2) ? r4.z : r4.w;
            }
            const int j = j0 + c;
            float z  = dsum + ssum2[c];
            float vn = (1.f - ALPHA) * v2s[j] + ALPHA * tanhf(z);
            v2n[j] = vn;
            __stcs(&out[(size_t)t * OUTW + RN + j], vn);
        }

        if (t < TSTEPS - 1) grid_sync(gen);
    }
}

// ---------------- launch ----------------
extern "C" void kernel_launch(void* const* d_in, const int* in_sizes, int n_in,
                              void* d_out, int out_size) {
    const float* x    = (const float*)d_in[0];
    const float* Win1 = (const float*)d_in[1];
    const float* W1   = (const float*)d_in[2];
    const float* Win2 = (const float*)d_in[3];
    const float* W2   = (const float*)d_in[4];
    float* out = (float*)d_out;
    (void)in_sizes; (void)n_in; (void)out_size;

    initKernel<<<(RN + 255) / 256, 256>>>();
    countKernel<<<250, 256>>>(W1, W2);
    scanKernel<<<2, 1024>>>();
    fillKernel<<<250, 256>>>(W1, W2);

    dim3 gg((RN + 127) / 128, (TSTEPS + 127) / 128);
    sgemmK<<<gg, 256>>>(x, Win1);

    esnKernel<<<NBLK, NTHR>>>(Win2, out);
}

// round 5
// speedup vs baseline: 2.0719x; 1.2322x over previous
#include <cuda_runtime.h>
#include <math.h>

// ---------------- problem constants ----------------
#define TSTEPS 1000
#define NIN    4096
#define RN     4000
#define OUTW   (2*RN)
#define ALPHA  0.5f

// ---------------- persistent loop config ----------------
#define NBLK   125             // 125 tiles x 32 columns = 4000
#define NTHR   1024

#define NNZ_CAP 1800000

// ---------------- device scratch ----------------
__device__ float          d_vals1[NNZ_CAP];
__device__ unsigned short d_rows1[NNZ_CAP];
__device__ float          d_vals2[NNZ_CAP];
__device__ unsigned short d_rows2[NNZ_CAP];
__device__ int            d_colptr1[RN+1];
__device__ int            d_colptr2[RN+1];
__device__ int            d_cntW1[8*RN];
__device__ int            d_cntW2[8*RN];
__device__ float          d_U1[TSTEPS*RN];    // x @ Win1   (16 MB)
__device__ float          d_U2[TSTEPS*RN];    // V1 @ Win2  (16 MB)
__device__ unsigned          g_in1;
__device__ volatile unsigned g_out1;
__device__ unsigned          g_in2;
__device__ volatile unsigned g_out2;

// ---------------- init ----------------
__global__ void initKernel() {
    if (threadIdx.x == 0) {
        g_in1 = 0u; g_out1 = 0u;
        g_in2 = 0u; g_out2 = 0u;
    }
}

// ---------------- sparse build: per-warp-range counts ----------------
__global__ void countKernel(const float* __restrict__ W1,
                            const float* __restrict__ W2) {
    int b = blockIdx.x;
    const float* W; int* cntW; int j0;
    if (b < 125) { W = W1; cntW = d_cntW1; j0 = b * 32; }
    else         { W = W2; cntW = d_cntW2; j0 = (b - 125) * 32; }
    int w = threadIdx.x >> 5, lane = threadIdx.x & 31;
    int j = j0 + lane;
    int c = 0;
    int i0 = w * 500, i1 = i0 + 500;
    for (int i = i0; i < i1; i++) c += (W[(size_t)i * RN + j] != 0.f);
    cntW[w * RN + j] = c;
}

// ---------------- exclusive scan ----------------
__global__ void scanKernel() {
    __shared__ int sA[4096], sB[4096];
    const int* cntW = (blockIdx.x == 0) ? d_cntW1 : d_cntW2;
    int* colptr     = (blockIdx.x == 0) ? d_colptr1 : d_colptr2;
    int tid = threadIdx.x;
    for (int i = tid; i < 4096; i += blockDim.x) {
        int tot = 0;
        if (i < RN)
            for (int w = 0; w < 8; w++) tot += cntW[w * RN + i];
        sA[i] = tot;
    }
    __syncthreads();
    int* src = sA; int* dst = sB;
    for (int off = 1; off < 4096; off <<= 1) {
        for (int i = tid; i < 4096; i += blockDim.x)
            dst[i] = src[i] + (i >= off ? src[i - off] : 0);
        __syncthreads();
        int* t = src; src = dst; dst = t;
    }
    for (int i = tid; i < RN; i += blockDim.x) colptr[i + 1] = src[i];
    if (tid == 0) colptr[0] = 0;
}

// ---------------- fill CSC ----------------
__global__ void fillKernel(const float* __restrict__ W1,
                           const float* __restrict__ W2) {
    int b = blockIdx.x;
    const float* W; const int* cntW; const int* colptr;
    float* vals; unsigned short* rows; int j0;
    if (b < 125) { W = W1; cntW = d_cntW1; colptr = d_colptr1;
                   vals = d_vals1; rows = d_rows1; j0 = b * 32; }
    else         { W = W2; cntW = d_cntW2; colptr = d_colptr2;
                   vals = d_vals2; rows = d_rows2; j0 = (b - 125) * 32; }
    int w = threadIdx.x >> 5, lane = threadIdx.x & 31;
    int j = j0 + lane;
    int p = colptr[j];
    for (int w2 = 0; w2 < 8; w2++)
        if (w2 < w) p += cntW[w2 * RN + j];
    int i0 = w * 500, i1 = i0 + 500;
    for (int i = i0; i < i1; i++) {
        float v = W[(size_t)i * RN + j];
        if (v != 0.f) { vals[p] = v; rows[p] = (unsigned short)i; p++; }
    }
}

// ---------------- SGEMM: d_U{1,2}[M,N] = A[M,K] @ B[K,N] --------------------
// C target selected by `which` INSIDE device code (device globals must not be
// passed as host-side kernel arguments — that was the R3/R4 bug).
__global__ __launch_bounds__(256) void sgemmK(const float* __restrict__ A,
                                              const float* __restrict__ B,
                                              int which,
                                              int M, int N, int K,
                                              int lda, int ldb, int ldc) {
    float* __restrict__ C = which ? d_U2 : d_U1;
    __shared__ float As[8][128];
    __shared__ float Bs[8][128];
    int tid = threadIdx.x;
    int tx = tid % 16, ty = tid / 16;
    int row0 = blockIdx.y * 128, col0 = blockIdx.x * 128;
    float acc[8][8];
#pragma unroll
    for (int i = 0; i < 8; i++)
#pragma unroll
        for (int j = 0; j < 8; j++) acc[i][j] = 0.f;

    int aRow = tid >> 1;
    int aCol = (tid & 1) * 4;
    int bRow = tid >> 5;
    int bCol = (tid & 31) * 4;

    for (int k0 = 0; k0 < K; k0 += 8) {
        float4 a4 = make_float4(0.f, 0.f, 0.f, 0.f);
        if (row0 + aRow < M)
            a4 = *(const float4*)(A + (size_t)(row0 + aRow) * lda + k0 + aCol);
        As[aCol + 0][aRow] = a4.x; As[aCol + 1][aRow] = a4.y;
        As[aCol + 2][aRow] = a4.z; As[aCol + 3][aRow] = a4.w;

        float4 b4 = make_float4(0.f, 0.f, 0.f, 0.f);
        if (col0 + bCol < N)
            b4 = *(const float4*)(B + (size_t)(k0 + bRow) * ldb + col0 + bCol);
        *(float4*)(&Bs[bRow][bCol]) = b4;
        __syncthreads();

#pragma unroll
        for (int kk = 0; kk < 8; kk++) {
            float ar[8], br[8];
            *(float4*)(ar)     = *(float4*)(&As[kk][ty * 4]);
            *(float4*)(ar + 4) = *(float4*)(&As[kk][64 + ty * 4]);
            *(float4*)(br)     = *(float4*)(&Bs[kk][tx * 4]);
            *(float4*)(br + 4) = *(float4*)(&Bs[kk][64 + tx * 4]);
#pragma unroll
            for (int i = 0; i < 8; i++)
#pragma unroll
                for (int j = 0; j < 8; j++) acc[i][j] += ar[i] * br[j];
        }
        __syncthreads();
    }
#pragma unroll
    for (int i = 0; i < 8; i++) {
        int r = row0 + ((i < 4) ? (ty * 4 + i) : (64 + ty * 4 + i - 4));
        if (r >= M) continue;
#pragma unroll
        for (int half = 0; half < 2; half++) {
            int c = col0 + (half == 0 ? tx * 4 : 64 + tx * 4);
            if (c < N) {
                float4 v = make_float4(acc[i][half*4+0], acc[i][half*4+1],
                                       acc[i][half*4+2], acc[i][half*4+3]);
                *(float4*)(C + (size_t)r * ldc + c) = v;
            }
        }
    }
}

// ---------------- grid-wide barrier (R2-proven atomic counter) --------------
__device__ __forceinline__ void gsync(unsigned &gen,
                                      unsigned* barIn,
                                      volatile unsigned* barOut) {
    __syncthreads();
    if (threadIdx.x == 0) {
        gen++;
        __threadfence();
        unsigned arrived = atomicAdd(barIn, 1u) + 1u;
        if (arrived == gen * (unsigned)NBLK) {
            *barOut = gen;                 // release
        } else {
            while (*barOut < gen) { }      // spin
        }
        __threadfence();
    }
    __syncthreads();
}

// ---------------- sparse-only recurrence (shared by both chains) ------------
// Block b owns columns [b*32, b*32+32). CSC slice stays in global (L1-resident
// after step 1). State rows live in `out` (stride OUTW, column offset ofs).
// v(t) = 0.5*v(t-1) + 0.5*tanh( v(t-1)@W + U[t] ),  v(-1)=0
__device__ __forceinline__ void esn_chain(const int* __restrict__ colptr,
                                          const float* __restrict__ gvals,
                                          const unsigned short* __restrict__ grows,
                                          const float* __restrict__ U,
                                          float* __restrict__ out, int ofs,
                                          unsigned* barIn,
                                          volatile unsigned* barOut) {
    __shared__ float vs[RN];
    __shared__ int s_cst[33];

    const int tid  = threadIdx.x;
    const int lane = tid & 31;
    const int wrp  = tid >> 5;          // 0..31 -> one column each
    const int j0   = blockIdx.x * 32;
    unsigned gen = 0;

    if (tid < 33) s_cst[tid] = __ldg(&colptr[j0 + tid]);

    // t = 0 : v(0) = 0.5*tanh(U[0])
    if (tid < 32) {
        int j = j0 + tid;
        out[(size_t)0 * OUTW + ofs + j] = ALPHA * tanhf(__ldg(&U[j]));
    }
    gsync(gen, barIn, barOut);          // also orders s_cst for the loop

    for (int t = 1; t < TSTEPS; t++) {
        // stage v(t-1) into smem (bypass L1: written by other SMs)
        const float4* vp = reinterpret_cast<const float4*>(
            out + (size_t)(t - 1) * OUTW + ofs);
        for (int i = tid; i < RN / 4; i += NTHR)
            reinterpret_cast<float4*>(vs)[i] = __ldcg(vp + i);
        __syncthreads();

        // warp w -> column j0+w
        {
            const int ps = s_cst[wrp];
            const int pe = s_cst[wrp + 1];
            float acc = 0.f;
            for (int p = ps + lane; p < pe; p += 32)
                acc += __ldg(&gvals[p]) * vs[__ldg(&grows[p])];
#pragma unroll
            for (int off = 16; off > 0; off >>= 1)
                acc += __shfl_down_sync(0xffffffffu, acc, off);
            if (lane == 0) {
                const int j = j0 + wrp;
                float z  = acc + __ldg(&U[(size_t)t * RN + j]);
                float vn = (1.f - ALPHA) * vs[j] + ALPHA * tanhf(z);
                out[(size_t)t * OUTW + ofs + j] = vn;
            }
        }
        gsync(gen, barIn, barOut);
    }
}

__global__ __launch_bounds__(NTHR, 1) void esn1Kernel(float* __restrict__ out) {
    esn_chain(d_colptr1, d_vals1, d_rows1, d_U1, out, 0, &g_in1, &g_out1);
}

__global__ __launch_bounds__(NTHR, 1) void esn2Kernel(float* __restrict__ out) {
    esn_chain(d_colptr2, d_vals2, d_rows2, d_U2, out, RN, &g_in2, &g_out2);
}

// ---------------- launch ----------------
extern "C" void kernel_launch(void* const* d_in, const int* in_sizes, int n_in,
                              void* d_out, int out_size) {
    const float* x    = (const float*)d_in[0];
    const float* Win1 = (const float*)d_in[1];
    const float* W1   = (const float*)d_in[2];
    const float* Win2 = (const float*)d_in[3];
    const float* W2   = (const float*)d_in[4];
    float* out = (float*)d_out;
    (void)in_sizes; (void)n_in; (void)out_size;

    initKernel<<<1, 32>>>();
    countKernel<<<250, 256>>>(W1, W2);
    scanKernel<<<2, 1024>>>();
    fillKernel<<<250, 256>>>(W1, W2);

    dim3 gg((RN + 127) / 128, (TSTEPS + 127) / 128);
    // U1 = x[1000,4096] @ Win1[4096,4000]
    sgemmK<<<gg, 256>>>(x, Win1, 0, TSTEPS, RN, NIN, NIN, RN, RN);

    // v1 chain -> out[:, 0:4000]
    esn1Kernel<<<NBLK, NTHR>>>(out);

    // U2 = V1[1000,4000] @ Win2[4000,4000]  (V1 rows in out, stride OUTW)
    sgemmK<<<gg, 256>>>(out, Win2, 1, TSTEPS, RN, RN, OUTW, RN, RN);

    // v2 chain -> out[:, 4000:8000]
    esn2Kernel<<<NBLK, NTHR>>>(out);
}

// round 6
// speedup vs baseline: 2.1007x; 1.0139x over previous
#include <cuda_runtime.h>
#include <math.h>

// ---------------- problem constants ----------------
#define TSTEPS 1000
#define NIN    4096
#define RN     4000
#define OUTW   (2*RN)
#define ALPHA  0.5f

// ---------------- persistent loop config ----------------
#define NBLK   125             // 125 tiles x 32 columns = 4000
#define NTHR   1024

#define NNZ_CAP 1800000

// ---------------- device scratch ----------------
__device__ float          d_vals1[NNZ_CAP];
__device__ unsigned short d_rows1[NNZ_CAP];
__device__ float          d_vals2[NNZ_CAP];
__device__ unsigned short d_rows2[NNZ_CAP];
__device__ int            d_colptr1[RN+1];
__device__ int            d_colptr2[RN+1];
__device__ int            d_cntW1[8*RN];
__device__ int            d_cntW2[8*RN];
__device__ float          d_U1[TSTEPS*RN];    // x @ Win1   (16 MB)
__device__ float          d_U2[TSTEPS*RN];    // V1 @ Win2  (16 MB)
__device__ unsigned          g_in1;
__device__ volatile unsigned g_out1;
__device__ unsigned          g_in2;
__device__ volatile unsigned g_out2;

// ---------------- packed f32x2 helpers (sm_103a FFMA2 pipe) -----------------
__device__ __forceinline__ unsigned long long dupf2(float v) {
    unsigned long long r;
    asm("mov.b64 %0, {%1, %2};" : "=l"(r) : "f"(v), "f"(v));
    return r;
}
__device__ __forceinline__ void fmaf2(unsigned long long &d,
                                      unsigned long long a,
                                      unsigned long long b) {
    asm("fma.rn.f32x2 %0, %1, %2, %0;" : "+l"(d) : "l"(a), "l"(b));
}
__device__ __forceinline__ float2 unpk(unsigned long long v) {
    float2 r;
    asm("mov.b64 {%0, %1}, %2;" : "=f"(r.x), "=f"(r.y) : "l"(v));
    return r;
}

// ---------------- init ----------------
__global__ void initKernel() {
    if (threadIdx.x == 0) {
        g_in1 = 0u; g_out1 = 0u;
        g_in2 = 0u; g_out2 = 0u;
    }
}

// ---------------- sparse build: per-warp-range counts ----------------
__global__ void countKernel(const float* __restrict__ W1,
                            const float* __restrict__ W2) {
    int b = blockIdx.x;
    const float* W; int* cntW; int j0;
    if (b < 125) { W = W1; cntW = d_cntW1; j0 = b * 32; }
    else         { W = W2; cntW = d_cntW2; j0 = (b - 125) * 32; }
    int w = threadIdx.x >> 5, lane = threadIdx.x & 31;
    int j = j0 + lane;
    int c = 0;
    int i0 = w * 500, i1 = i0 + 500;
    for (int i = i0; i < i1; i++) c += (W[(size_t)i * RN + j] != 0.f);
    cntW[w * RN + j] = c;
}

// ---------------- exclusive scan ----------------
__global__ void scanKernel() {
    __shared__ int sA[4096], sB[4096];
    const int* cntW = (blockIdx.x == 0) ? d_cntW1 : d_cntW2;
    int* colptr     = (blockIdx.x == 0) ? d_colptr1 : d_colptr2;
    int tid = threadIdx.x;
    for (int i = tid; i < 4096; i += blockDim.x) {
        int tot = 0;
        if (i < RN)
            for (int w = 0; w < 8; w++) tot += cntW[w * RN + i];
        sA[i] = tot;
    }
    __syncthreads();
    int* src = sA; int* dst = sB;
    for (int off = 1; off < 4096; off <<= 1) {
        for (int i = tid; i < 4096; i += blockDim.x)
            dst[i] = src[i] + (i >= off ? src[i - off] : 0);
        __syncthreads();
        int* t = src; src = dst; dst = t;
    }
    for (int i = tid; i < RN; i += blockDim.x) colptr[i + 1] = src[i];
    if (tid == 0) colptr[0] = 0;
}

// ---------------- fill CSC ----------------
__global__ void fillKernel(const float* __restrict__ W1,
                           const float* __restrict__ W2) {
    int b = blockIdx.x;
    const float* W; const int* cntW; const int* colptr;
    float* vals; unsigned short* rows; int j0;
    if (b < 125) { W = W1; cntW = d_cntW1; colptr = d_colptr1;
                   vals = d_vals1; rows = d_rows1; j0 = b * 32; }
    else         { W = W2; cntW = d_cntW2; colptr = d_colptr2;
                   vals = d_vals2; rows = d_rows2; j0 = (b - 125) * 32; }
    int w = threadIdx.x >> 5, lane = threadIdx.x & 31;
    int j = j0 + lane;
    int p = colptr[j];
    for (int w2 = 0; w2 < 8; w2++)
        if (w2 < w) p += cntW[w2 * RN + j];
    int i0 = w * 500, i1 = i0 + 500;
    for (int i = i0; i < i1; i++) {
        float v = W[(size_t)i * RN + j];
        if (v != 0.f) { vals[p] = v; rows[p] = (unsigned short)i; p++; }
    }
}

// ---------------- SGEMM (f32x2 packed, reg double-buffer) -------------------
// C = which ? d_U2 : d_U1 (resolved in device code; device globals must never
// be passed as host-side kernel args). C[M,N] = A[M,K] @ B[K,N].
// Accumulators pair two consecutive OUTPUT ROWS in one 64-bit register; the
// row pairs come for free out of the float4 smem loads.
__global__ __launch_bounds__(256) void sgemmK(const float* __restrict__ A,
                                              const float* __restrict__ B,
                                              int which,
                                              int M, int N, int K,
                                              int lda, int ldb, int ldc) {
    float* __restrict__ C = which ? d_U2 : d_U1;
    __shared__ float As[8][128];
    __shared__ float Bs[8][128];
    int tid = threadIdx.x;
    int tx = tid % 16, ty = tid / 16;
    int row0 = blockIdx.y * 128, col0 = blockIdx.x * 128;

    unsigned long long acc2[4][8];   // [row-pair][col]
#pragma unroll
    for (int p = 0; p < 4; p++)
#pragma unroll
        for (int j = 0; j < 8; j++) acc2[p][j] = 0ull;

    const int aRow = tid >> 1;
    const int aCol = (tid & 1) * 4;
    const int bRow = tid >> 5;
    const int bCol = (tid & 31) * 4;

    // prologue: fetch tile 0 into registers
    float4 a4 = make_float4(0.f, 0.f, 0.f, 0.f);
    if (row0 + aRow < M)
        a4 = *(const float4*)(A + (size_t)(row0 + aRow) * lda + aCol);
    float4 b4 = make_float4(0.f, 0.f, 0.f, 0.f);
    if (col0 + bCol < N)
        b4 = *(const float4*)(B + (size_t)bRow * ldb + col0 + bCol);

    for (int k0 = 0; k0 < K; k0 += 8) {
        // commit prefetched tile to smem
        As[aCol + 0][aRow] = a4.x; As[aCol + 1][aRow] = a4.y;
        As[aCol + 2][aRow] = a4.z; As[aCol + 3][aRow] = a4.w;
        *(float4*)(&Bs[bRow][bCol]) = b4;
        __syncthreads();

        // prefetch next tile (hidden behind the compute below)
        if (k0 + 8 < K) {
            if (row0 + aRow < M)
                a4 = *(const float4*)(A + (size_t)(row0 + aRow) * lda + k0 + 8 + aCol);
            if (col0 + bCol < N)
                b4 = *(const float4*)(B + (size_t)(k0 + 8 + bRow) * ldb + col0 + bCol);
        }

#pragma unroll
        for (int kk = 0; kk < 8; kk++) {
            float4 a0 = *(const float4*)(&As[kk][ty * 4]);
            float4 a1 = *(const float4*)(&As[kk][64 + ty * 4]);
            float4 bb0 = *(const float4*)(&Bs[kk][tx * 4]);
            float4 bb1 = *(const float4*)(&Bs[kk][64 + tx * 4]);
            unsigned long long ap[4];
            ap[0] = reinterpret_cast<const ulonglong2*>(&a0)->x;  // rows (0,1)
            ap[1] = reinterpret_cast<const ulonglong2*>(&a0)->y;  // rows (2,3)
            ap[2] = reinterpret_cast<const ulonglong2*>(&a1)->x;  // rows (4,5)
            ap[3] = reinterpret_cast<const ulonglong2*>(&a1)->y;  // rows (6,7)
            unsigned long long bd[8];
            bd[0] = dupf2(bb0.x); bd[1] = dupf2(bb0.y);
            bd[2] = dupf2(bb0.z); bd[3] = dupf2(bb0.w);
            bd[4] = dupf2(bb1.x); bd[5] = dupf2(bb1.y);
            bd[6] = dupf2(bb1.z); bd[7] = dupf2(bb1.w);
#pragma unroll
            for (int p = 0; p < 4; p++)
#pragma unroll
                for (int j = 0; j < 8; j++)
                    fmaf2(acc2[p][j], ap[p], bd[j]);
        }
        __syncthreads();
    }

    // epilogue: unpack row pairs, store float4 per row half
#pragma unroll
    for (int p = 0; p < 4; p++) {
        float2 u[8];
#pragma unroll
        for (int j = 0; j < 8; j++) u[j] = unpk(acc2[p][j]);
#pragma unroll
        for (int h = 0; h < 2; h++) {
            int i = 2 * p + h;
            int r = row0 + ((i < 4) ? (ty * 4 + i) : (64 + ty * 4 + i - 4));
            if (r >= M) continue;
            float4 v0 = make_float4(h ? u[0].y : u[0].x, h ? u[1].y : u[1].x,
                                    h ? u[2].y : u[2].x, h ? u[3].y : u[3].x);
            float4 v1 = make_float4(h ? u[4].y : u[4].x, h ? u[5].y : u[5].x,
                                    h ? u[6].y : u[6].x, h ? u[7].y : u[7].x);
            int c0 = col0 + tx * 4;
            int c1 = col0 + 64 + tx * 4;
            if (c0 < N) *(float4*)(C + (size_t)r * ldc + c0) = v0;
            if (c1 < N) *(float4*)(C + (size_t)r * ldc + c1) = v1;
        }
    }
}

// ---------------- grid-wide barrier (proven atomic counter) -----------------
__device__ __forceinline__ void gsync(unsigned &gen,
                                      unsigned* barIn,
                                      volatile unsigned* barOut) {
    __syncthreads();
    if (threadIdx.x == 0) {
        gen++;
        __threadfence();
        unsigned arrived = atomicAdd(barIn, 1u) + 1u;
        if (arrived == gen * (unsigned)NBLK) {
            *barOut = gen;                 // release
        } else {
            while (*barOut < gen) { }      // spin
        }
        __threadfence();
    }
    __syncthreads();
}

// ---------------- sparse-only recurrence (shared by both chains) ------------
__device__ __forceinline__ void esn_chain(const int* __restrict__ colptr,
                                          const float* __restrict__ gvals,
                                          const unsigned short* __restrict__ grows,
                                          const float* __restrict__ U,
                                          float* __restrict__ out, int ofs,
                                          unsigned* barIn,
                                          volatile unsigned* barOut) {
    __shared__ float vs[RN];
    __shared__ int s_cst[33];

    const int tid  = threadIdx.x;
    const int lane = tid & 31;
    const int wrp  = tid >> 5;          // 0..31 -> one column each
    const int j0   = blockIdx.x * 32;
    unsigned gen = 0;

    if (tid < 33) s_cst[tid] = __ldg(&colptr[j0 + tid]);

    // t = 0 : v(0) = 0.5*tanh(U[0])
    if (tid < 32) {
        int j = j0 + tid;
        out[(size_t)0 * OUTW + ofs + j] = ALPHA * tanhf(__ldg(&U[j]));
    }
    gsync(gen, barIn, barOut);          // also orders s_cst for the loop

    for (int t = 1; t < TSTEPS; t++) {
        // stage v(t-1) into smem (bypass L1: written by other SMs)
        const float4* vp = reinterpret_cast<const float4*>(
            out + (size_t)(t - 1) * OUTW + ofs);
        for (int i = tid; i < RN / 4; i += NTHR)
            reinterpret_cast<float4*>(vs)[i] = __ldcg(vp + i);
        __syncthreads();

        // warp w -> column j0+w
        {
            const int ps = s_cst[wrp];
            const int pe = s_cst[wrp + 1];
            float acc = 0.f;
            for (int p = ps + lane; p < pe; p += 32)
                acc += __ldg(&gvals[p]) * vs[__ldg(&grows[p])];
#pragma unroll
            for (int off = 16; off > 0; off >>= 1)
                acc += __shfl_down_sync(0xffffffffu, acc, off);
            if (lane == 0) {
                const int j = j0 + wrp;
                float z  = acc + __ldg(&U[(size_t)t * RN + j]);
                float vn = (1.f - ALPHA) * vs[j] + ALPHA * tanhf(z);
                out[(size_t)t * OUTW + ofs + j] = vn;
            }
        }
        gsync(gen, barIn, barOut);
    }
}

__global__ __launch_bounds__(NTHR, 1) void esn1Kernel(float* __restrict__ out) {
    esn_chain(d_colptr1, d_vals1, d_rows1, d_U1, out, 0, &g_in1, &g_out1);
}

__global__ __launch_bounds__(NTHR, 1) void esn2Kernel(float* __restrict__ out) {
    esn_chain(d_colptr2, d_vals2, d_rows2, d_U2, out, RN, &g_in2, &g_out2);
}

// ---------------- launch ----------------
extern "C" void kernel_launch(void* const* d_in, const int* in_sizes, int n_in,
                              void* d_out, int out_size) {
    const float* x    = (const float*)d_in[0];
    const float* Win1 = (const float*)d_in[1];
    const float* W1   = (const float*)d_in[2];
    const float* Win2 = (const float*)d_in[3];
    const float* W2   = (const float*)d_in[4];
    float* out = (float*)d_out;
    (void)in_sizes; (void)n_in; (void)out_size;

    initKernel<<<1, 32>>>();
    countKernel<<<250, 256>>>(W1, W2);
    scanKernel<<<2, 1024>>>();
    fillKernel<<<250, 256>>>(W1, W2);

    dim3 gg((RN + 127) / 128, (TSTEPS + 127) / 128);
    // U1 = x[1000,4096] @ Win1[4096,4000]
    sgemmK<<<gg, 256>>>(x, Win1, 0, TSTEPS, RN, NIN, NIN, RN, RN);

    // v1 chain -> out[:, 0:4000]
    esn1Kernel<<<NBLK, NTHR>>>(out);

    // U2 = V1[1000,4000] @ Win2[4000,4000]  (V1 rows in out, stride OUTW)
    sgemmK<<<gg, 256>>>(out, Win2, 1, TSTEPS, RN, RN, OUTW, RN, RN);

    // v2 chain -> out[:, 4000:8000]
    esn2Kernel<<<NBLK, NTHR>>>(out);
}